// round 9
// baseline (speedup 1.0000x reference)
#include <cuda_runtime.h>
#include <math.h>

// Problem constants
#define Bn 4
#define Sn 8
#define Nn 1024
#define Fn 6
#define Hn 64
#define Ln 3
#define Kn 16
#define Dn 3
#define Pn (Bn*Sn*Nn)        // 32768 points
#define PH (Pn*Hn)           // 2097152

// Scratch (static device globals; no runtime allocation allowed)
__device__ float g_scratch[4 * PH];   // x, q(=q+pe), k(=k+pe), v
__device__ int   g_nidx[Pn * Kn];
__device__ float g_xs[Bn * Sn * Hn];

__device__ __forceinline__ float gelu_tanh(float x) {
    float x3 = x * x * x;
    float arg = 0.7978845608028654f * (x + 0.044715f * x3);
    float t;
    asm("tanh.approx.f32 %0, %1;" : "=f"(t) : "f"(arg));
    return 0.5f * x * (1.0f + t);
}

// ---------------------------------------------------------------------------
// x = points @ w_in + b_in
// ---------------------------------------------------------------------------
__global__ void k_inproj(const float* __restrict__ pts,
                         const float* __restrict__ w_in,
                         const float* __restrict__ b_in,
                         float* __restrict__ x) {
    __shared__ float sw[Fn * Hn];
    __shared__ float sb[Hn];
    int tid = threadIdx.x;
    for (int i = tid; i < Fn * Hn; i += 256) sw[i] = w_in[i];
    if (tid < Hn) sb[tid] = b_in[tid];
    __syncthreads();
    int idx = blockIdx.x * 256 + tid;          // p*64 + h
    int p = idx >> 6, h = idx & 63;
    const float* pp = pts + p * Fn;
    float acc = sb[h];
#pragma unroll
    for (int f = 0; f < Fn; ++f) acc = fmaf(pp[f], sw[f * Hn + h], acc);
    x[idx] = acc;
}

// ---------------------------------------------------------------------------
// KNN: per (b,s) chunk of 1024 points, each query keeps sorted top-16 dists.
// ---------------------------------------------------------------------------
__global__ void k_knn(const float* __restrict__ pts, int* __restrict__ nidx) {
    __shared__ float sx[Nn], sy[Nn], sz[Nn];
    int bs = blockIdx.x >> 2;
    int qblk = blockIdx.x & 3;
    int base = bs * Nn;
    for (int j = threadIdx.x; j < Nn; j += 256) {
        const float* pp = pts + (base + j) * Fn;
        sx[j] = pp[0]; sy[j] = pp[1]; sz[j] = pp[2];
    }
    __syncthreads();
    int qi = qblk * 256 + threadIdx.x;
    float qx = sx[qi], qy = sy[qi], qz = sz[qi];
    float bd[Kn]; int bi[Kn];
#pragma unroll
    for (int u = 0; u < Kn; ++u) { bd[u] = 3.4e38f; bi[u] = 0; }
    for (int j = 0; j < Nn; ++j) {
        float dx = sx[j] - qx, dy = sy[j] - qy, dz = sz[j] - qz;
        float d = fmaf(dx, dx, fmaf(dy, dy, dz * dz));
        if (d < bd[Kn - 1]) {
#pragma unroll
            for (int u = Kn - 1; u > 0; --u) {
                if (bd[u] > d) {
                    bool take_prev = bd[u - 1] > d;
                    bd[u] = take_prev ? bd[u - 1] : d;
                    bi[u] = take_prev ? bi[u - 1] : j;
                }
            }
            if (bd[0] > d) { bd[0] = d; bi[0] = j; }
        }
    }
    int gp = base + qi;
#pragma unroll
    for (int u = 0; u < Kn; ++u) nidx[gp * Kn + u] = base + bi[u];
}

// ---------------------------------------------------------------------------
// Fused QKV GEMM with positional encoding folded in:
//   q = x @ Wq + bq + pos @ Wpe + bpe
//   k = x @ Wk + bk + pos @ Wpe + bpe
//   v = x @ Wv + bv
// M-tile=64, grid 512, 256 threads, each thread 2x8.  A transposed in shared.
// ---------------------------------------------------------------------------
__global__ __launch_bounds__(256) void k_qkv(const float* __restrict__ A,
                                             const float* __restrict__ pts,
                                             const float* __restrict__ Wq,
                                             const float* __restrict__ Wk,
                                             const float* __restrict__ Wv,
                                             const float* __restrict__ bq,
                                             const float* __restrict__ bk,
                                             const float* __restrict__ bv,
                                             const float* __restrict__ Wpe,
                                             const float* __restrict__ bpe,
                                             float* __restrict__ q,
                                             float* __restrict__ k,
                                             float* __restrict__ v) {
    __shared__ float Ast[64][64];    // transposed: Ast[k][row]
    __shared__ float Ws[64][64];
    int tid = threadIdx.x;
    int rowbase = blockIdx.x * 64;
    // Load A tile transposed (1024 float4, 4 per thread)
#pragma unroll
    for (int it = 0; it < 4; ++it) {
        int t = tid + it * 256;
        int r = t & 63;
        int kc = (t >> 6) << 2;
        float4 v4 = *(const float4*)(A + (rowbase + r) * 64 + kc);
        Ast[kc + 0][r] = v4.x; Ast[kc + 1][r] = v4.y;
        Ast[kc + 2][r] = v4.z; Ast[kc + 3][r] = v4.w;
    }
    int r0 = (tid >> 3) << 1;       // 2 rows
    int c0 = (tid & 7) << 3;        // 8 cols
    // positions for my 2 rows
    float posr[2][3];
#pragma unroll
    for (int i = 0; i < 2; ++i) {
        const float* pp = pts + (rowbase + r0 + i) * Fn;
        posr[i][0] = pp[0]; posr[i][1] = pp[1]; posr[i][2] = pp[2];
    }
    // pe weights for my 8 cols
    float wpe[3][8], bpeA[8];
#pragma unroll
    for (int d = 0; d < 3; ++d) {
        *(float4*)&wpe[d][0] = *(const float4*)(Wpe + d * 64 + c0);
        *(float4*)&wpe[d][4] = *(const float4*)(Wpe + d * 64 + c0 + 4);
    }
    *(float4*)&bpeA[0] = *(const float4*)(bpe + c0);
    *(float4*)&bpeA[4] = *(const float4*)(bpe + c0 + 4);

    const float* Wmat[3] = {Wq, Wk, Wv};
    const float* bias[3] = {bq, bk, bv};
    float* outp[3] = {q, k, v};
#pragma unroll 1
    for (int m = 0; m < 3; ++m) {
        __syncthreads();   // Ast ready (m=0) / previous Ws consumers done
#pragma unroll
        for (int it = 0; it < 4; ++it) {
            int t = tid + it * 256;
            ((float4*)Ws)[t] = ((const float4*)Wmat[m])[t];
        }
        __syncthreads();
        float acc[2][8];
#pragma unroll
        for (int i = 0; i < 2; ++i)
#pragma unroll
            for (int j = 0; j < 8; ++j) acc[i][j] = 0.0f;
#pragma unroll 8
        for (int kk = 0; kk < 64; ++kk) {
            float a[2], b[8];
            a[0] = Ast[kk][r0];
            a[1] = Ast[kk][r0 + 1];
            float4 b0 = *(const float4*)&Ws[kk][c0];
            float4 b1 = *(const float4*)&Ws[kk][c0 + 4];
            b[0] = b0.x; b[1] = b0.y; b[2] = b0.z; b[3] = b0.w;
            b[4] = b1.x; b[5] = b1.y; b[6] = b1.z; b[7] = b1.w;
#pragma unroll
            for (int i = 0; i < 2; ++i)
#pragma unroll
                for (int j = 0; j < 8; ++j)
                    acc[i][j] = fmaf(a[i], b[j], acc[i][j]);
        }
        float bb[8];
        *(float4*)&bb[0] = *(const float4*)(bias[m] + c0);
        *(float4*)&bb[4] = *(const float4*)(bias[m] + c0 + 4);
        float* op = outp[m];
#pragma unroll
        for (int i = 0; i < 2; ++i) {
            int row = rowbase + r0 + i;
            float o[8];
#pragma unroll
            for (int j = 0; j < 8; ++j) o[j] = acc[i][j] + bb[j];
            if (m < 2) {
                float px = posr[i][0], py = posr[i][1], pz = posr[i][2];
#pragma unroll
                for (int j = 0; j < 8; ++j) {
                    float pe = bpeA[j];
                    pe = fmaf(px, wpe[0][j], pe);
                    pe = fmaf(py, wpe[1][j], pe);
                    pe = fmaf(pz, wpe[2][j], pe);
                    o[j] += pe;
                }
            }
            *(float4*)(op + row * 64 + c0)     = make_float4(o[0], o[1], o[2], o[3]);
            *(float4*)(op + row * 64 + c0 + 4) = make_float4(o[4], o[5], o[6], o[7]);
        }
    }
}

// ---------------------------------------------------------------------------
// Fused: neighbor attention -> att@Wo+bo -> gelu -> +x residual -> LayerNorm.
// M-tile=64, grid 512, 256 threads.  Phase A: 8 warps x 8 points of attention
// (Wo staged to smem concurrently), results to As[64][65].  Phase B: GEMM from
// smem, epilogue with register LayerNorm over 8-lane shfl groups.  In-place x.
//
// Score algebra (exact reassociation):
//   score_n = 0.125*(dot(u,kpe_j) + c0 + cx*dx + cy*dy + cz*dz) + ba
// with u = qp .* Wa (per-channel), c0 = dot(u,bpd), c{x,y,z} = dot(u,Wpd_d).
// c* reduced ONCE per point; per-neighbor work = 2 loads + 2 FMAs + reduce.
// ---------------------------------------------------------------------------
__global__ __launch_bounds__(256) void k_attn_o(const float* __restrict__ pts,
                                                const float* __restrict__ qp,
                                                const float* __restrict__ kpe,
                                                const float* __restrict__ v,
                                                const int* __restrict__ nidx,
                                                const float* __restrict__ Wpd,
                                                const float* __restrict__ bpd,
                                                const float* __restrict__ Wa,
                                                const float* __restrict__ ba,
                                                const float* __restrict__ Wo,
                                                const float* __restrict__ bo,
                                                const float* __restrict__ ln_s,
                                                const float* __restrict__ ln_b,
                                                float* __restrict__ x) {
    __shared__ float As[64][65];
    __shared__ float Wos[64][64];
    __shared__ float swpd[3 * Hn];
    __shared__ float sbpd[Hn];
    __shared__ float swa[Hn];
    __shared__ float sba;
    int tid = threadIdx.x;
    int warp = tid >> 5, lane = tid & 31;
    int rowbase = blockIdx.x * 64;
    // Stage Wo into smem (overlaps with Phase A attention work below)
#pragma unroll
    for (int it = 0; it < 4; ++it) {
        int t = tid + it * 256;
        ((float4*)Wos)[t] = ((const float4*)Wo)[t];
    }
    for (int i = tid; i < 3 * Hn; i += 256) swpd[i] = Wpd[i];
    if (tid < Hn) { sbpd[tid] = bpd[tid]; swa[tid] = Wa[tid]; }
    if (tid == 0) sba = ba[0];
    __syncthreads();

    int h0 = lane, h1 = lane + 32;
    float wa0 = swa[h0], wa1 = swa[h1];
    float wpd00 = swpd[h0], wpd10 = swpd[Hn + h0], wpd20 = swpd[2 * Hn + h0];
    float wpd01 = swpd[h1], wpd11 = swpd[Hn + h1], wpd21 = swpd[2 * Hn + h1];
    float bpd0 = sbpd[h0], bpd1 = sbpd[h1];

    // --- Phase A: attention for 8 points per warp ---
#pragma unroll 1
    for (int t = 0; t < 8; ++t) {
        int r = warp * 8 + t;
        int p = rowbase + r;
        float qp0 = qp[p * 64 + h0];
        float qp1 = qp[p * 64 + h1];
        float u0 = qp0 * wa0, u1 = qp1 * wa1;
        // per-point scalar coefficients: c0 = dot(u,bpd), c{x,y,z} = dot(u,Wpd_d)
        float cp0 = fmaf(u1, bpd1,  u0 * bpd0);
        float cpx = fmaf(u1, wpd01, u0 * wpd00);
        float cpy = fmaf(u1, wpd11, u0 * wpd10);
        float cpz = fmaf(u1, wpd21, u0 * wpd20);
#pragma unroll
        for (int o = 16; o; o >>= 1) {
            cp0 += __shfl_xor_sync(0xffffffffu, cp0, o);
            cpx += __shfl_xor_sync(0xffffffffu, cpx, o);
            cpy += __shfl_xor_sync(0xffffffffu, cpy, o);
            cpz += __shfl_xor_sync(0xffffffffu, cpz, o);
        }
        const float* pp = pts + p * Fn;
        float pix = pp[0], piy = pp[1], piz = pp[2];
        float a[Kn]; int jj[Kn];
#pragma unroll
        for (int n = 0; n < Kn; ++n) {
            int j = nidx[p * Kn + n];
            jj[n] = j;
            const float* pj = pts + j * Fn;
            float dx = pj[0] - pix, dy = pj[1] - piy, dz = pj[2] - piz;
            float s = fmaf(u0, kpe[j * 64 + h0], u1 * kpe[j * 64 + h1]);
#pragma unroll
            for (int o = 16; o; o >>= 1) s += __shfl_xor_sync(0xffffffffu, s, o);
            float pdsc = cp0;
            pdsc = fmaf(dx, cpx, pdsc);
            pdsc = fmaf(dy, cpy, pdsc);
            pdsc = fmaf(dz, cpz, pdsc);
            a[n] = (s + pdsc) * 0.125f + sba;
        }
        float m = a[0];
#pragma unroll
        for (int n = 1; n < Kn; ++n) m = fmaxf(m, a[n]);
        float ssum = 0.0f;
#pragma unroll
        for (int n = 0; n < Kn; ++n) { a[n] = expf(a[n] - m); ssum += a[n]; }
        float inv = 1.0f / ssum;
        float acc0 = 0.0f, acc1 = 0.0f;
#pragma unroll
        for (int n = 0; n < Kn; ++n) {
            float w = a[n] * inv;
            int j = jj[n];
            acc0 = fmaf(w, v[j * 64 + h0], acc0);
            acc1 = fmaf(w, v[j * 64 + h1], acc1);
        }
        As[r][h0] = acc0;
        As[r][h1] = acc1;
    }
    __syncthreads();

    // --- Phase B: O-GEMM + gelu + residual + LayerNorm ---
    int r0 = (tid >> 3) << 1;   // 2 rows
    int c0 = (tid & 7) << 3;    // 8 cols
    float acc[2][8];
#pragma unroll
    for (int i = 0; i < 2; ++i)
#pragma unroll
        for (int j = 0; j < 8; ++j) acc[i][j] = 0.0f;
#pragma unroll 8
    for (int kk = 0; kk < 64; ++kk) {
        float a[2], b[8];
        a[0] = As[r0][kk];
        a[1] = As[r0 + 1][kk];
        float4 b0 = *(const float4*)&Wos[kk][c0];
        float4 b1 = *(const float4*)&Wos[kk][c0 + 4];
        b[0] = b0.x; b[1] = b0.y; b[2] = b0.z; b[3] = b0.w;
        b[4] = b1.x; b[5] = b1.y; b[6] = b1.z; b[7] = b1.w;
#pragma unroll
        for (int i = 0; i < 2; ++i)
#pragma unroll
            for (int j = 0; j < 8; ++j)
                acc[i][j] = fmaf(a[i], b[j], acc[i][j]);
    }
    float bb[8], ss[8], sb2[8];
    *(float4*)&bb[0]  = *(const float4*)(bo + c0);
    *(float4*)&bb[4]  = *(const float4*)(bo + c0 + 4);
    *(float4*)&ss[0]  = *(const float4*)(ln_s + c0);
    *(float4*)&ss[4]  = *(const float4*)(ln_s + c0 + 4);
    *(float4*)&sb2[0] = *(const float4*)(ln_b + c0);
    *(float4*)&sb2[4] = *(const float4*)(ln_b + c0 + 4);
#pragma unroll
    for (int i = 0; i < 2; ++i) {
        int row = rowbase + r0 + i;
        float4 r40 = *(const float4*)(x + row * 64 + c0);
        float4 r41 = *(const float4*)(x + row * 64 + c0 + 4);
        float o[8];
        o[0] = r40.x + gelu_tanh(acc[i][0] + bb[0]);
        o[1] = r40.y + gelu_tanh(acc[i][1] + bb[1]);
        o[2] = r40.z + gelu_tanh(acc[i][2] + bb[2]);
        o[3] = r40.w + gelu_tanh(acc[i][3] + bb[3]);
        o[4] = r41.x + gelu_tanh(acc[i][4] + bb[4]);
        o[5] = r41.y + gelu_tanh(acc[i][5] + bb[5]);
        o[6] = r41.z + gelu_tanh(acc[i][6] + bb[6]);
        o[7] = r41.w + gelu_tanh(acc[i][7] + bb[7]);
        // LayerNorm across the row (8 lanes x 8 cols), 8-lane shfl groups
        float s = 0.0f, sq = 0.0f;
#pragma unroll
        for (int j = 0; j < 8; ++j) { s += o[j]; sq = fmaf(o[j], o[j], sq); }
#pragma unroll
        for (int msk = 1; msk < 8; msk <<= 1) {
            s  += __shfl_xor_sync(0xffffffffu, s, msk);
            sq += __shfl_xor_sync(0xffffffffu, sq, msk);
        }
        float mu = s * (1.0f / 64.0f);
        float var = sq * (1.0f / 64.0f) - mu * mu;
        float rstd = rsqrtf(var + 1e-6f);
        float w[8];
#pragma unroll
        for (int j = 0; j < 8; ++j) w[j] = (o[j] - mu) * rstd * ss[j] + sb2[j];
        *(float4*)(x + row * 64 + c0)     = make_float4(w[0], w[1], w[2], w[3]);
        *(float4*)(x + row * 64 + c0 + 4) = make_float4(w[4], w[5], w[6], w[7]);
    }
}

// ---------------------------------------------------------------------------
// Max over N (1024 points per (b,s))
// ---------------------------------------------------------------------------
__global__ void k_maxn(const float* __restrict__ x, float* __restrict__ xs) {
    __shared__ float red[4][Hn];
    int bs = blockIdx.x, tid = threadIdx.x;
    int h = tid & 63, seg = tid >> 6;
    float m = -3.4e38f;
    const float* xp = x + (bs * Nn + seg * 256) * 64 + h;
#pragma unroll 8
    for (int n = 0; n < 256; ++n) m = fmaxf(m, xp[n * 64]);
    red[seg][h] = m;
    __syncthreads();
    if (tid < Hn) {
        float r2 = fmaxf(fmaxf(red[0][tid], red[1][tid]),
                         fmaxf(red[2][tid], red[3][tid]));
        xs[bs * Hn + tid] = r2;
    }
}

// ---------------------------------------------------------------------------
// Final encoder layer over S=8 tokens per batch + LN + max over S.
// ---------------------------------------------------------------------------
__global__ void k_final(const float* __restrict__ xs,
                        const float* __restrict__ Wek, const float* __restrict__ bek,
                        const float* __restrict__ Weq, const float* __restrict__ beq,
                        const float* __restrict__ Wev, const float* __restrict__ bev,
                        const float* __restrict__ We1, const float* __restrict__ be1,
                        const float* __restrict__ We2, const float* __restrict__ be2,
                        const float* __restrict__ ln2_s, const float* __restrict__ ln2_b,
                        float* __restrict__ out) {
    __shared__ float X[Sn][Hn], Q[Sn][Hn], Ksm[Sn][Hn], V[Sn][Hn];
    __shared__ float AW[Sn][Sn], H1[Sn][Hn], Y[Sn][Hn];
    int b = blockIdx.x, tid = threadIdx.x;
    for (int i = tid; i < Sn * Hn; i += 256) ((float*)X)[i] = xs[b * Sn * Hn + i];
    __syncthreads();
    for (int i = tid; i < Sn * Hn; i += 256) {
        int t = i >> 6, h = i & 63;
        float aq = beq[h], ak = bek[h], av = bev[h];
#pragma unroll 8
        for (int kk = 0; kk < Hn; ++kk) {
            float xv = X[t][kk];
            aq = fmaf(xv, Weq[kk * Hn + h], aq);
            ak = fmaf(xv, Wek[kk * Hn + h], ak);
            av = fmaf(xv, Wev[kk * Hn + h], av);
        }
        Q[t][h] = aq; Ksm[t][h] = ak; V[t][h] = av;
    }
    __syncthreads();
    if (tid < Sn * Sn) {
        int t = tid >> 3, s2 = tid & 7;
        float acc = 0.0f;
#pragma unroll 8
        for (int kk = 0; kk < Hn; ++kk) acc = fmaf(Q[t][kk], Ksm[s2][kk], acc);
        AW[t][s2] = acc * 0.125f;
    }
    __syncthreads();
    if (tid < Sn) {
        float m = AW[tid][0];
#pragma unroll
        for (int s2 = 1; s2 < Sn; ++s2) m = fmaxf(m, AW[tid][s2]);
        float sum = 0.0f;
#pragma unroll
        for (int s2 = 0; s2 < Sn; ++s2) { float e = expf(AW[tid][s2] - m); AW[tid][s2] = e; sum += e; }
        float inv = 1.0f / sum;
#pragma unroll
        for (int s2 = 0; s2 < Sn; ++s2) AW[tid][s2] *= inv;
    }
    __syncthreads();
    for (int i = tid; i < Sn * Hn; i += 256) {
        int t = i >> 6, h = i & 63;
        float acc = 0.0f;
#pragma unroll
        for (int s2 = 0; s2 < Sn; ++s2) acc = fmaf(AW[t][s2], V[s2][h], acc);
        Y[t][h] = acc;
    }
    __syncthreads();
    for (int i = tid; i < Sn * Hn; i += 256) {
        int t = i >> 6, h = i & 63;
        float acc = be1[h];
#pragma unroll 8
        for (int kk = 0; kk < Hn; ++kk) acc = fmaf(Y[t][kk], We1[kk * Hn + h], acc);
        H1[t][h] = gelu_tanh(acc);
    }
    __syncthreads();
    for (int i = tid; i < Sn * Hn; i += 256) {
        int t = i >> 6, h = i & 63;
        float acc = be2[h];
#pragma unroll 8
        for (int kk = 0; kk < Hn; ++kk) acc = fmaf(H1[t][kk], We2[kk * Hn + h], acc);
        Y[t][h] = acc + X[t][h];
    }
    __syncthreads();
    {
        int warp = tid >> 5, lane = tid & 31;
        float v0 = Y[warp][lane], v1 = Y[warp][lane + 32];
        float s = v0 + v1, sq = v0 * v0 + v1 * v1;
#pragma unroll
        for (int o = 16; o; o >>= 1) {
            s += __shfl_xor_sync(0xffffffffu, s, o);
            sq += __shfl_xor_sync(0xffffffffu, sq, o);
        }
        float mu = s * (1.0f / 64.0f);
        float var = sq * (1.0f / 64.0f) - mu * mu;
        float r = rsqrtf(var + 1e-6f);
        Y[warp][lane]      = (v0 - mu) * r * ln2_s[lane] + ln2_b[lane];
        Y[warp][lane + 32] = (v1 - mu) * r * ln2_s[lane + 32] + ln2_b[lane + 32];
    }
    __syncthreads();
    if (tid < Hn) {
        float m = Y[0][tid];
#pragma unroll
        for (int t = 1; t < Sn; ++t) m = fmaxf(m, Y[t][tid]);
        out[b * Hn + tid] = m;
    }
}

// ---------------------------------------------------------------------------
// Launcher
// ---------------------------------------------------------------------------
extern "C" void kernel_launch(void* const* d_in, const int* in_sizes, int n_in,
                              void* d_out, int out_size) {
    (void)in_sizes; (void)n_in; (void)out_size;
    const float* pts  = (const float*)d_in[0];
    const float* w_in = (const float*)d_in[1];
    const float* b_in = (const float*)d_in[2];
    const float* Wq   = (const float*)d_in[3];
    const float* bq   = (const float*)d_in[4];
    const float* Wk   = (const float*)d_in[5];
    const float* bk   = (const float*)d_in[6];
    const float* Wv   = (const float*)d_in[7];
    const float* bv   = (const float*)d_in[8];
    const float* Wpe  = (const float*)d_in[9];
    const float* bpe  = (const float*)d_in[10];
    const float* Wpd  = (const float*)d_in[11];
    const float* bpd  = (const float*)d_in[12];
    const float* Wa   = (const float*)d_in[13];
    const float* ba   = (const float*)d_in[14];
    const float* Wo   = (const float*)d_in[15];
    const float* bo   = (const float*)d_in[16];
    const float* ln_s = (const float*)d_in[17];
    const float* ln_b = (const float*)d_in[18];
    const float* Wek  = (const float*)d_in[19];
    const float* bek  = (const float*)d_in[20];
    const float* Weq  = (const float*)d_in[21];
    const float* beq  = (const float*)d_in[22];
    const float* Wev  = (const float*)d_in[23];
    const float* bev  = (const float*)d_in[24];
    const float* We1  = (const float*)d_in[25];
    const float* be1  = (const float*)d_in[26];
    const float* We2  = (const float*)d_in[27];
    const float* be2  = (const float*)d_in[28];
    const float* ln2s = (const float*)d_in[29];
    const float* ln2b = (const float*)d_in[30];
    float* out = (float*)d_out;

    float* scratch = nullptr;
    int* nidx = nullptr;
    float* xs = nullptr;
    cudaGetSymbolAddress((void**)&scratch, g_scratch);
    cudaGetSymbolAddress((void**)&nidx, g_nidx);
    cudaGetSymbolAddress((void**)&xs, g_xs);
    float* x = scratch;
    float* q = scratch + PH;
    float* k = scratch + 2 * PH;
    float* v = scratch + 3 * PH;

    k_inproj<<<PH / 256, 256>>>(pts, w_in, b_in, x);
    k_knn<<<Bn * Sn * 4, 256>>>(pts, nidx);

    for (int l = 0; l < Ln; ++l) {
        k_qkv<<<Pn / 64, 256>>>(x, pts,
                                Wq + l * Hn * Hn, Wk + l * Hn * Hn, Wv + l * Hn * Hn,
                                bq + l * Hn, bk + l * Hn, bv + l * Hn,
                                Wpe + l * Dn * Hn, bpe + l * Hn,
                                q, k, v);
        k_attn_o<<<Pn / 64, 256>>>(pts, q, k, v, nidx,
                                   Wpd + l * Dn * Hn, bpd + l * Hn,
                                   Wa + l * Hn, ba + l,
                                   Wo + l * Hn * Hn, bo + l * Hn,
                                   ln_s + l * Hn, ln_b + l * Hn, x);
    }

    k_maxn<<<Bn * Sn, 256>>>(x, xs);
    k_final<<<Bn, 256>>>(xs, Wek, bek, Weq, beq, Wev, bev,
                         We1, be1, We2, be2, ln2s, ln2b, out);
}

// round 11
// speedup vs baseline: 1.2097x; 1.2097x over previous
#include <cuda_runtime.h>
#include <math.h>

// Problem constants
#define Bn 4
#define Sn 8
#define Nn 1024
#define Fn 6
#define Hn 64
#define Ln 3
#define Kn 16
#define Dn 3
#define Pn (Bn*Sn*Nn)        // 32768 points
#define PH (Pn*Hn)           // 2097152

// Scratch (static device globals; no runtime allocation allowed)
__device__ float g_scratch[5 * PH];   // x, q(=q+pe), k(=k+pe), v, att
__device__ int   g_nidx[Pn * Kn];
__device__ float g_xs[Bn * Sn * Hn];

__device__ __forceinline__ float gelu_tanh(float x) {
    float x3 = x * x * x;
    float arg = 0.7978845608028654f * (x + 0.044715f * x3);
    float t;
    asm("tanh.approx.f32 %0, %1;" : "=f"(t) : "f"(arg));
    return 0.5f * x * (1.0f + t);
}

// ---------------------------------------------------------------------------
// x = points @ w_in + b_in
// ---------------------------------------------------------------------------
__global__ void k_inproj(const float* __restrict__ pts,
                         const float* __restrict__ w_in,
                         const float* __restrict__ b_in,
                         float* __restrict__ x) {
    __shared__ float sw[Fn * Hn];
    __shared__ float sb[Hn];
    int tid = threadIdx.x;
    for (int i = tid; i < Fn * Hn; i += 256) sw[i] = w_in[i];
    if (tid < Hn) sb[tid] = b_in[tid];
    __syncthreads();
    int idx = blockIdx.x * 256 + tid;          // p*64 + h
    int p = idx >> 6, h = idx & 63;
    const float* pp = pts + p * Fn;
    float acc = sb[h];
#pragma unroll
    for (int f = 0; f < Fn; ++f) acc = fmaf(pp[f], sw[f * Hn + h], acc);
    x[idx] = acc;
}

// ---------------------------------------------------------------------------
// KNN: per (b,s) chunk of 1024 points, each query keeps sorted top-16 dists.
// ---------------------------------------------------------------------------
__global__ void k_knn(const float* __restrict__ pts, int* __restrict__ nidx) {
    __shared__ float sx[Nn], sy[Nn], sz[Nn];
    int bs = blockIdx.x >> 2;
    int qblk = blockIdx.x & 3;
    int base = bs * Nn;
    for (int j = threadIdx.x; j < Nn; j += 256) {
        const float* pp = pts + (base + j) * Fn;
        sx[j] = pp[0]; sy[j] = pp[1]; sz[j] = pp[2];
    }
    __syncthreads();
    int qi = qblk * 256 + threadIdx.x;
    float qx = sx[qi], qy = sy[qi], qz = sz[qi];
    float bd[Kn]; int bi[Kn];
#pragma unroll
    for (int u = 0; u < Kn; ++u) { bd[u] = 3.4e38f; bi[u] = 0; }
    for (int j = 0; j < Nn; ++j) {
        float dx = sx[j] - qx, dy = sy[j] - qy, dz = sz[j] - qz;
        float d = fmaf(dx, dx, fmaf(dy, dy, dz * dz));
        if (d < bd[Kn - 1]) {
#pragma unroll
            for (int u = Kn - 1; u > 0; --u) {
                if (bd[u] > d) {
                    bool take_prev = bd[u - 1] > d;
                    bd[u] = take_prev ? bd[u - 1] : d;
                    bi[u] = take_prev ? bi[u - 1] : j;
                }
            }
            if (bd[0] > d) { bd[0] = d; bi[0] = j; }
        }
    }
    int gp = base + qi;
#pragma unroll
    for (int u = 0; u < Kn; ++u) nidx[gp * Kn + u] = base + bi[u];
}

// ---------------------------------------------------------------------------
// Fused QKV GEMM with positional encoding folded in (128-row tile, 4x8/thr):
//   q = x @ Wq + bq + pos @ Wpe + bpe
//   k = x @ Wk + bk + pos @ Wpe + bpe
//   v = x @ Wv + bv
// ---------------------------------------------------------------------------
__global__ __launch_bounds__(256) void k_qkv(const float* __restrict__ A,
                                             const float* __restrict__ pts,
                                             const float* __restrict__ Wq,
                                             const float* __restrict__ Wk,
                                             const float* __restrict__ Wv,
                                             const float* __restrict__ bq,
                                             const float* __restrict__ bk,
                                             const float* __restrict__ bv,
                                             const float* __restrict__ Wpe,
                                             const float* __restrict__ bpe,
                                             float* __restrict__ q,
                                             float* __restrict__ k,
                                             float* __restrict__ v) {
    __shared__ float Ast[64][128];
    __shared__ float Ws[64][64];
    int tid = threadIdx.x;
    int rowbase = blockIdx.x * 128;
#pragma unroll
    for (int it = 0; it < 8; ++it) {
        int t = tid + it * 256;
        int r = t & 127;
        int kc = (t >> 7) << 2;
        float4 v4 = *(const float4*)(A + (rowbase + r) * 64 + kc);
        Ast[kc + 0][r] = v4.x; Ast[kc + 1][r] = v4.y;
        Ast[kc + 2][r] = v4.z; Ast[kc + 3][r] = v4.w;
    }
    int r0 = (tid >> 3) << 2;       // 4 rows
    int c0 = (tid & 7) << 3;        // 8 cols
    float posr[4][3];
#pragma unroll
    for (int i = 0; i < 4; ++i) {
        const float* pp = pts + (rowbase + r0 + i) * Fn;
        posr[i][0] = pp[0]; posr[i][1] = pp[1]; posr[i][2] = pp[2];
    }
    float wpe[3][8], bpeA[8];
#pragma unroll
    for (int d = 0; d < 3; ++d) {
        *(float4*)&wpe[d][0] = *(const float4*)(Wpe + d * 64 + c0);
        *(float4*)&wpe[d][4] = *(const float4*)(Wpe + d * 64 + c0 + 4);
    }
    *(float4*)&bpeA[0] = *(const float4*)(bpe + c0);
    *(float4*)&bpeA[4] = *(const float4*)(bpe + c0 + 4);

    const float* Wmat[3] = {Wq, Wk, Wv};
    const float* bias[3] = {bq, bk, bv};
    float* outp[3] = {q, k, v};
#pragma unroll 1
    for (int m = 0; m < 3; ++m) {
        __syncthreads();
#pragma unroll
        for (int it = 0; it < 4; ++it) {
            int t = tid + it * 256;
            ((float4*)Ws)[t] = ((const float4*)Wmat[m])[t];
        }
        __syncthreads();
        float acc[4][8];
#pragma unroll
        for (int i = 0; i < 4; ++i)
#pragma unroll
            for (int j = 0; j < 8; ++j) acc[i][j] = 0.0f;
#pragma unroll 8
        for (int kk = 0; kk < 64; ++kk) {
            float a[4], b[8];
#pragma unroll
            for (int i = 0; i < 4; ++i) a[i] = Ast[kk][r0 + i];
            float4 b0 = *(const float4*)&Ws[kk][c0];
            float4 b1 = *(const float4*)&Ws[kk][c0 + 4];
            b[0] = b0.x; b[1] = b0.y; b[2] = b0.z; b[3] = b0.w;
            b[4] = b1.x; b[5] = b1.y; b[6] = b1.z; b[7] = b1.w;
#pragma unroll
            for (int i = 0; i < 4; ++i)
#pragma unroll
                for (int j = 0; j < 8; ++j)
                    acc[i][j] = fmaf(a[i], b[j], acc[i][j]);
        }
        float bb[8];
        *(float4*)&bb[0] = *(const float4*)(bias[m] + c0);
        *(float4*)&bb[4] = *(const float4*)(bias[m] + c0 + 4);
        float* op = outp[m];
#pragma unroll
        for (int i = 0; i < 4; ++i) {
            int row = rowbase + r0 + i;
            float o[8];
#pragma unroll
            for (int j = 0; j < 8; ++j) o[j] = acc[i][j] + bb[j];
            if (m < 2) {
                float px = posr[i][0], py = posr[i][1], pz = posr[i][2];
#pragma unroll
                for (int j = 0; j < 8; ++j) {
                    float pe = bpeA[j];
                    pe = fmaf(px, wpe[0][j], pe);
                    pe = fmaf(py, wpe[1][j], pe);
                    pe = fmaf(pz, wpe[2][j], pe);
                    o[j] += pe;
                }
            }
            *(float4*)(op + row * 64 + c0)     = make_float4(o[0], o[1], o[2], o[3]);
            *(float4*)(op + row * 64 + c0 + 4) = make_float4(o[4], o[5], o[6], o[7]);
        }
    }
}

// ---------------------------------------------------------------------------
// Neighbor attention: ONE point per warp (grid Pn/8 = 4096 blocks x 256thr),
// maximum latency hiding.  Score algebra (exact reassociation):
//   score_n = 0.125*(dot(u,kpe_j) + c0 + cx*dx + cy*dy + cz*dz) + ba
// with u = qp .* Wa, c0 = dot(u,bpd), c{x,y,z} = dot(u,Wpd_d) reduced once.
// ---------------------------------------------------------------------------
__global__ void k_attn(const float* __restrict__ pts,
                       const float* __restrict__ qp,
                       const float* __restrict__ kpe,
                       const float* __restrict__ v,
                       const int* __restrict__ nidx,
                       const float* __restrict__ Wpd,
                       const float* __restrict__ bpd,
                       const float* __restrict__ Wa,
                       const float* __restrict__ ba,
                       float* __restrict__ att) {
    __shared__ float swpd[3 * Hn];
    __shared__ float sbpd[Hn];
    __shared__ float swa[Hn];
    __shared__ float sba;
    int tid = threadIdx.x;
    for (int i = tid; i < 3 * Hn; i += 256) swpd[i] = Wpd[i];
    if (tid < Hn) { sbpd[tid] = bpd[tid]; swa[tid] = Wa[tid]; }
    if (tid == 0) sba = ba[0];
    __syncthreads();
    int warp = tid >> 5, lane = tid & 31;
    int p = blockIdx.x * 8 + warp;
    int h0 = lane, h1 = lane + 32;
    float qp0 = qp[p * 64 + h0];
    float qp1 = qp[p * 64 + h1];
    float u0 = qp0 * swa[h0], u1 = qp1 * swa[h1];
    // per-point scalar coefficients
    float cp0 = fmaf(u1, sbpd[h1],          u0 * sbpd[h0]);
    float cpx = fmaf(u1, swpd[h1],          u0 * swpd[h0]);
    float cpy = fmaf(u1, swpd[Hn + h1],     u0 * swpd[Hn + h0]);
    float cpz = fmaf(u1, swpd[2 * Hn + h1], u0 * swpd[2 * Hn + h0]);
#pragma unroll
    for (int o = 16; o; o >>= 1) {
        cp0 += __shfl_xor_sync(0xffffffffu, cp0, o);
        cpx += __shfl_xor_sync(0xffffffffu, cpx, o);
        cpy += __shfl_xor_sync(0xffffffffu, cpy, o);
        cpz += __shfl_xor_sync(0xffffffffu, cpz, o);
    }
    const float* pp = pts + p * Fn;
    float pix = pp[0], piy = pp[1], piz = pp[2];
    float a[Kn]; int jj[Kn];
#pragma unroll
    for (int n = 0; n < Kn; ++n) {
        int j = nidx[p * Kn + n];
        jj[n] = j;
        const float* pj = pts + j * Fn;
        float dx = pj[0] - pix, dy = pj[1] - piy, dz = pj[2] - piz;
        float s = fmaf(u0, kpe[j * 64 + h0], u1 * kpe[j * 64 + h1]);
#pragma unroll
        for (int o = 16; o; o >>= 1) s += __shfl_xor_sync(0xffffffffu, s, o);
        float pdsc = cp0;
        pdsc = fmaf(dx, cpx, pdsc);
        pdsc = fmaf(dy, cpy, pdsc);
        pdsc = fmaf(dz, cpz, pdsc);
        a[n] = (s + pdsc) * 0.125f + sba;
    }
    float m = a[0];
#pragma unroll
    for (int n = 1; n < Kn; ++n) m = fmaxf(m, a[n]);
    float ssum = 0.0f;
#pragma unroll
    for (int n = 0; n < Kn; ++n) { a[n] = expf(a[n] - m); ssum += a[n]; }
    float inv = 1.0f / ssum;
    float acc0 = 0.0f, acc1 = 0.0f;
#pragma unroll
    for (int n = 0; n < Kn; ++n) {
        float w = a[n] * inv;
        int j = jj[n];
        acc0 = fmaf(w, v[j * 64 + h0], acc0);
        acc1 = fmaf(w, v[j * 64 + h1], acc1);
    }
    att[p * 64 + h0] = acc0;
    att[p * 64 + h1] = acc1;
}

// ---------------------------------------------------------------------------
// O-GEMM + gelu + residual + LayerNorm (128-row tile, 4x8/thr, grid 256):
//   x = LN(x + gelu(att @ Wo + bo)) * ln_s + ln_b   (in place on x)
// ---------------------------------------------------------------------------
__global__ __launch_bounds__(256) void k_gemmO_ln(const float* __restrict__ att,
                                                  const float* __restrict__ Wo,
                                                  const float* __restrict__ bo,
                                                  const float* __restrict__ ln_s,
                                                  const float* __restrict__ ln_b,
                                                  float* __restrict__ x) {
    __shared__ float As[128][65];
    __shared__ float Wos[64][64];
    int tid = threadIdx.x;
    int rowbase = blockIdx.x * 128;
    // stage att tile row-major (2048 float4)
#pragma unroll
    for (int it = 0; it < 8; ++it) {
        int t = tid + it * 256;
        int r = t >> 4;
        int c = (t & 15) << 2;
        float4 v4 = *(const float4*)(att + (rowbase + r) * 64 + c);
        As[r][c + 0] = v4.x; As[r][c + 1] = v4.y;
        As[r][c + 2] = v4.z; As[r][c + 3] = v4.w;
    }
#pragma unroll
    for (int it = 0; it < 4; ++it) {
        int t = tid + it * 256;
        ((float4*)Wos)[t] = ((const float4*)Wo)[t];
    }
    __syncthreads();
    int r0 = (tid >> 3) << 2;   // 4 rows
    int c0 = (tid & 7) << 3;    // 8 cols
    float acc[4][8];
#pragma unroll
    for (int i = 0; i < 4; ++i)
#pragma unroll
        for (int j = 0; j < 8; ++j) acc[i][j] = 0.0f;
#pragma unroll 8
    for (int kk = 0; kk < 64; ++kk) {
        float a[4], b[8];
#pragma unroll
        for (int i = 0; i < 4; ++i) a[i] = As[r0 + i][kk];
        float4 b0 = *(const float4*)&Wos[kk][c0];
        float4 b1 = *(const float4*)&Wos[kk][c0 + 4];
        b[0] = b0.x; b[1] = b0.y; b[2] = b0.z; b[3] = b0.w;
        b[4] = b1.x; b[5] = b1.y; b[6] = b1.z; b[7] = b1.w;
#pragma unroll
        for (int i = 0; i < 4; ++i)
#pragma unroll
            for (int j = 0; j < 8; ++j)
                acc[i][j] = fmaf(a[i], b[j], acc[i][j]);
    }
    float bb[8], ss[8], sb2[8];
    *(float4*)&bb[0]  = *(const float4*)(bo + c0);
    *(float4*)&bb[4]  = *(const float4*)(bo + c0 + 4);
    *(float4*)&ss[0]  = *(const float4*)(ln_s + c0);
    *(float4*)&ss[4]  = *(const float4*)(ln_s + c0 + 4);
    *(float4*)&sb2[0] = *(const float4*)(ln_b + c0);
    *(float4*)&sb2[4] = *(const float4*)(ln_b + c0 + 4);
#pragma unroll
    for (int i = 0; i < 4; ++i) {
        int row = rowbase + r0 + i;
        float4 r40 = *(const float4*)(x + row * 64 + c0);
        float4 r41 = *(const float4*)(x + row * 64 + c0 + 4);
        float o[8];
        o[0] = r40.x + gelu_tanh(acc[i][0] + bb[0]);
        o[1] = r40.y + gelu_tanh(acc[i][1] + bb[1]);
        o[2] = r40.z + gelu_tanh(acc[i][2] + bb[2]);
        o[3] = r40.w + gelu_tanh(acc[i][3] + bb[3]);
        o[4] = r41.x + gelu_tanh(acc[i][4] + bb[4]);
        o[5] = r41.y + gelu_tanh(acc[i][5] + bb[5]);
        o[6] = r41.z + gelu_tanh(acc[i][6] + bb[6]);
        o[7] = r41.w + gelu_tanh(acc[i][7] + bb[7]);
        // LayerNorm across the row: 8-lane shfl groups hold the 64 cols
        float s = 0.0f, sq = 0.0f;
#pragma unroll
        for (int j = 0; j < 8; ++j) { s += o[j]; sq = fmaf(o[j], o[j], sq); }
#pragma unroll
        for (int msk = 1; msk < 8; msk <<= 1) {
            s  += __shfl_xor_sync(0xffffffffu, s, msk);
            sq += __shfl_xor_sync(0xffffffffu, sq, msk);
        }
        float mu = s * (1.0f / 64.0f);
        float var = sq * (1.0f / 64.0f) - mu * mu;
        float rstd = rsqrtf(var + 1e-6f);
        float w[8];
#pragma unroll
        for (int j = 0; j < 8; ++j) w[j] = (o[j] - mu) * rstd * ss[j] + sb2[j];
        *(float4*)(x + row * 64 + c0)     = make_float4(w[0], w[1], w[2], w[3]);
        *(float4*)(x + row * 64 + c0 + 4) = make_float4(w[4], w[5], w[6], w[7]);
    }
}

// ---------------------------------------------------------------------------
// Max over N (1024 points per (b,s))
// ---------------------------------------------------------------------------
__global__ void k_maxn(const float* __restrict__ x, float* __restrict__ xs) {
    __shared__ float red[4][Hn];
    int bs = blockIdx.x, tid = threadIdx.x;
    int h = tid & 63, seg = tid >> 6;
    float m = -3.4e38f;
    const float* xp = x + (bs * Nn + seg * 256) * 64 + h;
#pragma unroll 8
    for (int n = 0; n < 256; ++n) m = fmaxf(m, xp[n * 64]);
    red[seg][h] = m;
    __syncthreads();
    if (tid < Hn) {
        float r2 = fmaxf(fmaxf(red[0][tid], red[1][tid]),
                         fmaxf(red[2][tid], red[3][tid]));
        xs[bs * Hn + tid] = r2;
    }
}

// ---------------------------------------------------------------------------
// Final encoder layer over S=8 tokens per batch + LN + max over S.
// ---------------------------------------------------------------------------
__global__ void k_final(const float* __restrict__ xs,
                        const float* __restrict__ Wek, const float* __restrict__ bek,
                        const float* __restrict__ Weq, const float* __restrict__ beq,
                        const float* __restrict__ Wev, const float* __restrict__ bev,
                        const float* __restrict__ We1, const float* __restrict__ be1,
                        const float* __restrict__ We2, const float* __restrict__ be2,
                        const float* __restrict__ ln2_s, const float* __restrict__ ln2_b,
                        float* __restrict__ out) {
    __shared__ float X[Sn][Hn], Q[Sn][Hn], Ksm[Sn][Hn], V[Sn][Hn];
    __shared__ float AW[Sn][Sn], H1[Sn][Hn], Y[Sn][Hn];
    int b = blockIdx.x, tid = threadIdx.x;
    for (int i = tid; i < Sn * Hn; i += 256) ((float*)X)[i] = xs[b * Sn * Hn + i];
    __syncthreads();
    for (int i = tid; i < Sn * Hn; i += 256) {
        int t = i >> 6, h = i & 63;
        float aq = beq[h], ak = bek[h], av = bev[h];
#pragma unroll 8
        for (int kk = 0; kk < Hn; ++kk) {
            float xv = X[t][kk];
            aq = fmaf(xv, Weq[kk * Hn + h], aq);
            ak = fmaf(xv, Wek[kk * Hn + h], ak);
            av = fmaf(xv, Wev[kk * Hn + h], av);
        }
        Q[t][h] = aq; Ksm[t][h] = ak; V[t][h] = av;
    }
    __syncthreads();
    if (tid < Sn * Sn) {
        int t = tid >> 3, s2 = tid & 7;
        float acc = 0.0f;
#pragma unroll 8
        for (int kk = 0; kk < Hn; ++kk) acc = fmaf(Q[t][kk], Ksm[s2][kk], acc);
        AW[t][s2] = acc * 0.125f;
    }
    __syncthreads();
    if (tid < Sn) {
        float m = AW[tid][0];
#pragma unroll
        for (int s2 = 1; s2 < Sn; ++s2) m = fmaxf(m, AW[tid][s2]);
        float sum = 0.0f;
#pragma unroll
        for (int s2 = 0; s2 < Sn; ++s2) { float e = expf(AW[tid][s2] - m); AW[tid][s2] = e; sum += e; }
        float inv = 1.0f / sum;
#pragma unroll
        for (int s2 = 0; s2 < Sn; ++s2) AW[tid][s2] *= inv;
    }
    __syncthreads();
    for (int i = tid; i < Sn * Hn; i += 256) {
        int t = i >> 6, h = i & 63;
        float acc = 0.0f;
#pragma unroll
        for (int s2 = 0; s2 < Sn; ++s2) acc = fmaf(AW[t][s2], V[s2][h], acc);
        Y[t][h] = acc;
    }
    __syncthreads();
    for (int i = tid; i < Sn * Hn; i += 256) {
        int t = i >> 6, h = i & 63;
        float acc = be1[h];
#pragma unroll 8
        for (int kk = 0; kk < Hn; ++kk) acc = fmaf(Y[t][kk], We1[kk * Hn + h], acc);
        H1[t][h] = gelu_tanh(acc);
    }
    __syncthreads();
    for (int i = tid; i < Sn * Hn; i += 256) {
        int t = i >> 6, h = i & 63;
        float acc = be2[h];
#pragma unroll 8
        for (int kk = 0; kk < Hn; ++kk) acc = fmaf(H1[t][kk], We2[kk * Hn + h], acc);
        Y[t][h] = acc + X[t][h];
    }
    __syncthreads();
    {
        int warp = tid >> 5, lane = tid & 31;
        float v0 = Y[warp][lane], v1 = Y[warp][lane + 32];
        float s = v0 + v1, sq = v0 * v0 + v1 * v1;
#pragma unroll
        for (int o = 16; o; o >>= 1) {
            s += __shfl_xor_sync(0xffffffffu, s, o);
            sq += __shfl_xor_sync(0xffffffffu, sq, o);
        }
        float mu = s * (1.0f / 64.0f);
        float var = sq * (1.0f / 64.0f) - mu * mu;
        float r = rsqrtf(var + 1e-6f);
        Y[warp][lane]      = (v0 - mu) * r * ln2_s[lane] + ln2_b[lane];
        Y[warp][lane + 32] = (v1 - mu) * r * ln2_s[lane + 32] + ln2_b[lane + 32];
    }
    __syncthreads();
    if (tid < Hn) {
        float m = Y[0][tid];
#pragma unroll
        for (int t = 1; t < Sn; ++t) m = fmaxf(m, Y[t][tid]);
        out[b * Hn + tid] = m;
    }
}

// ---------------------------------------------------------------------------
// Launcher
// ---------------------------------------------------------------------------
extern "C" void kernel_launch(void* const* d_in, const int* in_sizes, int n_in,
                              void* d_out, int out_size) {
    (void)in_sizes; (void)n_in; (void)out_size;
    const float* pts  = (const float*)d_in[0];
    const float* w_in = (const float*)d_in[1];
    const float* b_in = (const float*)d_in[2];
    const float* Wq   = (const float*)d_in[3];
    const float* bq   = (const float*)d_in[4];
    const float* Wk   = (const float*)d_in[5];
    const float* bk   = (const float*)d_in[6];
    const float* Wv   = (const float*)d_in[7];
    const float* bv   = (const float*)d_in[8];
    const float* Wpe  = (const float*)d_in[9];
    const float* bpe  = (const float*)d_in[10];
    const float* Wpd  = (const float*)d_in[11];
    const float* bpd  = (const float*)d_in[12];
    const float* Wa   = (const float*)d_in[13];
    const float* ba   = (const float*)d_in[14];
    const float* Wo   = (const float*)d_in[15];
    const float* bo   = (const float*)d_in[16];
    const float* ln_s = (const float*)d_in[17];
    const float* ln_b = (const float*)d_in[18];
    const float* Wek  = (const float*)d_in[19];
    const float* bek  = (const float*)d_in[20];
    const float* Weq  = (const float*)d_in[21];
    const float* beq  = (const float*)d_in[22];
    const float* Wev  = (const float*)d_in[23];
    const float* bev  = (const float*)d_in[24];
    const float* We1  = (const float*)d_in[25];
    const float* be1  = (const float*)d_in[26];
    const float* We2  = (const float*)d_in[27];
    const float* be2  = (const float*)d_in[28];
    const float* ln2s = (const float*)d_in[29];
    const float* ln2b = (const float*)d_in[30];
    float* out = (float*)d_out;

    float* scratch = nullptr;
    int* nidx = nullptr;
    float* xs = nullptr;
    cudaGetSymbolAddress((void**)&scratch, g_scratch);
    cudaGetSymbolAddress((void**)&nidx, g_nidx);
    cudaGetSymbolAddress((void**)&xs, g_xs);
    float* x   = scratch;
    float* q   = scratch + PH;
    float* k   = scratch + 2 * PH;
    float* v   = scratch + 3 * PH;
    float* att = scratch + 4 * PH;

    k_inproj<<<PH / 256, 256>>>(pts, w_in, b_in, x);
    k_knn<<<Bn * Sn * 4, 256>>>(pts, nidx);

    for (int l = 0; l < Ln; ++l) {
        k_qkv<<<Pn / 128, 256>>>(x, pts,
                                 Wq + l * Hn * Hn, Wk + l * Hn * Hn, Wv + l * Hn * Hn,
                                 bq + l * Hn, bk + l * Hn, bv + l * Hn,
                                 Wpe + l * Dn * Hn, bpe + l * Hn,
                                 q, k, v);
        k_attn<<<Pn / 8, 256>>>(pts, q, k, v, nidx,
                                Wpd + l * Dn * Hn, bpd + l * Hn,
                                Wa + l * Hn, ba + l, att);
        k_gemmO_ln<<<Pn / 128, 256>>>(att, Wo + l * Hn * Hn, bo + l * Hn,
                                      ln_s + l * Hn, ln_b + l * Hn, x);
    }

    k_maxn<<<Bn * Sn, 256>>>(x, xs);
    k_final<<<Bn, 256>>>(xs, Wek, bek, Weq, beq, Wev, bev,
                         We1, be1, We2, be2, ln2s, ln2b, out);
}